// round 1
// baseline (speedup 1.0000x reference)
#include <cuda_runtime.h>

#define NN 50000
#define NE 800000
#define D  96
#define NG 128
#define OD 10

// ---------------- scratch (static device globals; no allocation) ----------------
__device__ float g_self[NN * D];
__device__ float g_msg [NN * D];
__device__ float g_h0  [NN * D];
__device__ float g_h1  [NN * D];
__device__ int   g_deg [NN];
__device__ int   g_cnt [NN];
__device__ int   g_ptr [NN + 1];
__device__ int   g_srcs[NE];
__device__ float g_emb [NG * D];

// ---------------- CSR build ----------------
__global__ void k_zero() {
    int i = blockIdx.x * blockDim.x + threadIdx.x;
    if (i < NN) { g_deg[i] = 0; g_cnt[i] = 0; }
}

__global__ void k_hist(const int* __restrict__ dst) {
    int e = blockIdx.x * blockDim.x + threadIdx.x;
    if (e < NE) atomicAdd(&g_deg[dst[e]], 1);
}

// single-block exclusive scan over g_deg -> g_ptr
__global__ void k_scan() {
    __shared__ int part[1024];
    const int T = 1024;
    const int C = (NN + T - 1) / T;  // 49
    int t = threadIdx.x;
    int base = t * C;
    int s = 0;
    for (int i = 0; i < C; i++) {
        int idx = base + i;
        if (idx < NN) s += g_deg[idx];
    }
    part[t] = s;
    __syncthreads();
    // Hillis-Steele inclusive scan
    for (int off = 1; off < T; off <<= 1) {
        int v = 0;
        if (t >= off) v = part[t - off];
        __syncthreads();
        if (t >= off) part[t] += v;
        __syncthreads();
    }
    int run = (t == 0) ? 0 : part[t - 1];
    for (int i = 0; i < C; i++) {
        int idx = base + i;
        if (idx < NN) { g_ptr[idx] = run; run += g_deg[idx]; }
    }
    if (t == T - 1) g_ptr[NN] = NE;
}

__global__ void k_fill(const int* __restrict__ src, const int* __restrict__ dst) {
    int e = blockIdx.x * blockDim.x + threadIdx.x;
    if (e < NE) {
        int d = dst[e];
        int pos = g_ptr[d] + atomicAdd(&g_cnt[d], 1);
        g_srcs[pos] = src[e];
    }
}

// ---------------- fused dual GEMM: self = h@W1, msg = h@W2 ----------------
// block = 256 threads, BM = 128 rows, full N = 96, K chunked by 32
__global__ void k_gemm_dual(const float* __restrict__ xin, int hcode,
                            const float* __restrict__ W1,
                            const float* __restrict__ W2) {
    const float* __restrict__ h = (hcode == 0) ? xin : ((hcode == 1) ? g_h0 : g_h1);

    __shared__ float shT[32][129];     // k-major h tile: shT[k][r]
    __shared__ float sw1[32][100];
    __shared__ float sw2[32][100];

    int t    = threadIdx.x;
    int row0 = blockIdx.x * 128;
    int r0   = (t >> 4) * 8;           // 0..120
    int c0   = (t & 15) * 6;           // 0..90

    float acc1[8][6];
    float acc2[8][6];
#pragma unroll
    for (int i = 0; i < 8; i++)
#pragma unroll
        for (int j = 0; j < 6; j++) { acc1[i][j] = 0.f; acc2[i][j] = 0.f; }

    for (int kc = 0; kc < D; kc += 32) {
        // load h tile (128x32) transposed into shared, coalesced on gmem
#pragma unroll
        for (int i = 0; i < 16; i++) {
            int lin = t + i * 256;
            int r = lin >> 5;
            int k = lin & 31;
            int grow = row0 + r;
            float v = (grow < NN) ? h[grow * D + kc + k] : 0.f;
            shT[k][r] = v;
        }
        // load W1/W2 chunk (32x96 each)
#pragma unroll
        for (int i = 0; i < 12; i++) {
            int lin = t + i * 256;
            int k = lin / 96;
            int n = lin - k * 96;
            sw1[k][n] = W1[(kc + k) * D + n];
            sw2[k][n] = W2[(kc + k) * D + n];
        }
        __syncthreads();

#pragma unroll
        for (int k = 0; k < 32; k++) {
            float a[8];
#pragma unroll
            for (int i = 0; i < 8; i++) a[i] = shT[k][r0 + i];
            float b1[6], b2[6];
#pragma unroll
            for (int j = 0; j < 6; j++) { b1[j] = sw1[k][c0 + j]; b2[j] = sw2[k][c0 + j]; }
#pragma unroll
            for (int i = 0; i < 8; i++)
#pragma unroll
                for (int j = 0; j < 6; j++) {
                    acc1[i][j] += a[i] * b1[j];
                    acc2[i][j] += a[i] * b2[j];
                }
        }
        __syncthreads();
    }

#pragma unroll
    for (int i = 0; i < 8; i++) {
        int grow = row0 + r0 + i;
        if (grow < NN) {
#pragma unroll
            for (int j = 0; j < 6; j++) {
                g_self[grow * D + c0 + j] = acc1[i][j];
                g_msg [grow * D + c0 + j] = acc2[i][j];
            }
        }
    }
}

// ---------------- aggregation: h_out = relu(self + sum_{in-edges} msg[src]) ----------------
// one warp per node; 3 dims per lane
__global__ void k_aggregate(int houtcode) {
    int gt   = blockIdx.x * blockDim.x + threadIdx.x;
    int w    = gt >> 5;
    int lane = gt & 31;
    if (w >= NN) return;
    float* __restrict__ hout = (houtcode == 1) ? g_h0 : g_h1;

    float a0 = 0.f, a1 = 0.f, a2 = 0.f;
    int s = g_ptr[w];
    int e = g_ptr[w + 1];
    for (int i = s; i < e; i++) {
        const float* __restrict__ m = g_msg + (size_t)g_srcs[i] * D;
        a0 += m[lane];
        a1 += m[lane + 32];
        a2 += m[lane + 64];
    }
    const float* __restrict__ sp = g_self + (size_t)w * D;
    hout[(size_t)w * D + lane     ] = fmaxf(sp[lane     ] + a0, 0.f);
    hout[(size_t)w * D + lane + 32] = fmaxf(sp[lane + 32] + a1, 0.f);
    hout[(size_t)w * D + lane + 64] = fmaxf(sp[lane + 64] + a2, 0.f);
}

// ---------------- graph pooling: segment_sum over sorted batch ----------------
__device__ __forceinline__ int lowerb(const int* __restrict__ a, int n, int v) {
    int lo = 0, hi = n;
    while (lo < hi) {
        int mid = (lo + hi) >> 1;
        if (a[mid] < v) lo = mid + 1; else hi = mid;
    }
    return lo;
}

// 128 blocks x 384 threads; final h lives in g_h0 after 3 layers
__global__ void k_pool(const int* __restrict__ batch) {
    __shared__ int   se[2];
    __shared__ float red[4][96];
    int g = blockIdx.x;
    int t = threadIdx.x;
    if (t == 0) se[0] = lowerb(batch, NN, g);
    if (t == 1) se[1] = lowerb(batch, NN, g + 1);
    __syncthreads();
    int d = t % 96;
    int q = t / 96;
    int s0 = se[0], s1 = se[1];
    float s = 0.f;
    for (int n = s0 + q; n < s1; n += 4) s += g_h0[(size_t)n * D + d];
    red[q][d] = s;
    __syncthreads();
    if (q == 0) g_emb[g * D + d] = red[0][d] + red[1][d] + red[2][d] + red[3][d];
}

// ---------------- MLP head ----------------
__global__ void k_mlp(const float* __restrict__ cw1, const float* __restrict__ cb1,
                      const float* __restrict__ cw2, const float* __restrict__ cb2,
                      float* __restrict__ out) {
    __shared__ float emb[96];
    __shared__ float hid[96];
    int g = blockIdx.x;
    int d = threadIdx.x;  // 96 threads
    emb[d] = g_emb[g * D + d];
    __syncthreads();
    float s = cb1[d];
#pragma unroll 8
    for (int k = 0; k < 96; k++) s += emb[k] * cw1[k * D + d];
    hid[d] = fmaxf(s, 0.f);
    __syncthreads();
    if (d < OD) {
        float o = cb2[d];
#pragma unroll 8
        for (int k = 0; k < 96; k++) o += hid[k] * cw2[k * OD + d];
        out[g * OD + d] = o;
    }
}

// ---------------- launch ----------------
extern "C" void kernel_launch(void* const* d_in, const int* in_sizes, int n_in,
                              void* d_out, int out_size) {
    const float* x     = (const float*)d_in[0];
    const int*   ei    = (const int*)  d_in[1];
    const int*   batch = (const int*)  d_in[2];
    const float* W1    = (const float*)d_in[3];
    const float* W2    = (const float*)d_in[4];
    const float* cw1   = (const float*)d_in[5];
    const float* cb1   = (const float*)d_in[6];
    const float* cw2   = (const float*)d_in[7];
    const float* cb2   = (const float*)d_in[8];
    float* out = (float*)d_out;

    const int* src = ei;        // edge_index[0]
    const int* dst = ei + NE;   // edge_index[1]

    // CSR build (edge structure is layer-invariant: build once per launch)
    k_zero<<<(NN + 255) / 256, 256>>>();
    k_hist<<<(NE + 255) / 256, 256>>>(dst);
    k_scan<<<1, 1024>>>();
    k_fill<<<(NE + 255) / 256, 256>>>(src, dst);

    const int gemm_grid = (NN + 127) / 128;
    const int agg_grid  = (NN * 32 + 255) / 256;

    // layer 0: x -> g_h0
    k_gemm_dual<<<gemm_grid, 256>>>(x, 0, W1 + 0 * D * D, W2 + 0 * D * D);
    k_aggregate<<<agg_grid, 256>>>(1);
    // layer 1: g_h0 -> g_h1
    k_gemm_dual<<<gemm_grid, 256>>>(x, 1, W1 + 1 * D * D, W2 + 1 * D * D);
    k_aggregate<<<agg_grid, 256>>>(2);
    // layer 2: g_h1 -> g_h0
    k_gemm_dual<<<gemm_grid, 256>>>(x, 2, W1 + 2 * D * D, W2 + 2 * D * D);
    k_aggregate<<<agg_grid, 256>>>(1);

    k_pool<<<NG, 384>>>(batch);
    k_mlp<<<NG, 96>>>(cw1, cb1, cw2, cb2, out);
}

// round 2
// speedup vs baseline: 1.3813x; 1.3813x over previous
#include <cuda_runtime.h>
#include <cstdint>

#define NN 50000
#define NE 800000
#define D  96
#define NG 128
#define OD 10

// ---------------- scratch (static device globals; no allocation) ----------------
__device__ __align__(16) float g_self[NN * D];
__device__ __align__(16) float g_msg [NN * D];
__device__ __align__(16) float g_h0  [NN * D];
__device__ __align__(16) float g_h1  [NN * D];
__device__ int   g_deg [NN];
__device__ int   g_cnt [NN];
__device__ int   g_ptr [NN + 1];
__device__ int   g_srcs[NE];
__device__ float g_emb [NG * D];

// ---------------- CSR build ----------------
__global__ void k_zero() {
    int i = blockIdx.x * blockDim.x + threadIdx.x;
    if (i < NN) { g_deg[i] = 0; g_cnt[i] = 0; }
}

__global__ void k_hist(const int* __restrict__ dst) {
    int e = blockIdx.x * blockDim.x + threadIdx.x;
    if (e < NE) atomicAdd(&g_deg[dst[e]], 1);
}

// single-block exclusive scan over g_deg -> g_ptr
__global__ void k_scan() {
    __shared__ int part[1024];
    const int T = 1024;
    const int C = (NN + T - 1) / T;  // 49
    int t = threadIdx.x;
    int base = t * C;
    int s = 0;
    for (int i = 0; i < C; i++) {
        int idx = base + i;
        if (idx < NN) s += g_deg[idx];
    }
    part[t] = s;
    __syncthreads();
    for (int off = 1; off < T; off <<= 1) {
        int v = 0;
        if (t >= off) v = part[t - off];
        __syncthreads();
        if (t >= off) part[t] += v;
        __syncthreads();
    }
    int run = (t == 0) ? 0 : part[t - 1];
    for (int i = 0; i < C; i++) {
        int idx = base + i;
        if (idx < NN) { g_ptr[idx] = run; run += g_deg[idx]; }
    }
    if (t == T - 1) g_ptr[NN] = NE;
}

__global__ void k_fill(const int* __restrict__ src, const int* __restrict__ dst) {
    int e = blockIdx.x * blockDim.x + threadIdx.x;
    if (e < NE) {
        int d = dst[e];
        int pos = g_ptr[d] + atomicAdd(&g_cnt[d], 1);
        g_srcs[pos] = src[e];
    }
}

// ---------------- tf32 helpers ----------------
__device__ __forceinline__ uint32_t f2tf32(float x) {
    uint32_t r;
    asm("cvt.rna.tf32.f32 %0, %1;" : "=r"(r) : "f"(x));
    return r;
}

__device__ __forceinline__ void mma_tf32(float* c,
                                         uint32_t a0, uint32_t a1, uint32_t a2, uint32_t a3,
                                         uint32_t b0, uint32_t b1) {
    asm volatile(
        "mma.sync.aligned.m16n8k8.row.col.f32.tf32.tf32.f32 "
        "{%0,%1,%2,%3}, {%4,%5,%6,%7}, {%8,%9}, {%0,%1,%2,%3};\n"
        : "+f"(c[0]), "+f"(c[1]), "+f"(c[2]), "+f"(c[3])
        : "r"(a0), "r"(a1), "r"(a2), "r"(a3), "r"(b0), "r"(b1));
}

// ---------------- fused dual GEMM on tensor cores (tf32) ----------------
// block = 256 threads (8 warps), tile M=128 (16 rows/warp), N=96, K chunked by 32.
// smem layouts stride-36 => fragment LDS banks (4*idx + k) % 32: conflict-free.
__global__ void k_gemm_dual_tc(const float* __restrict__ xin, int hcode,
                               const float* __restrict__ W1,
                               const float* __restrict__ W2) {
    const float* __restrict__ h = (hcode == 0) ? xin : ((hcode == 1) ? g_h0 : g_h1);

    __shared__ uint32_t sA [128 * 36];   // sA[r*36 + k]
    __shared__ uint32_t sW1[96 * 36];    // sW1[n*36 + k]
    __shared__ uint32_t sW2[96 * 36];

    int t    = threadIdx.x;
    int warp = t >> 5;
    int lane = t & 31;
    int gq   = lane >> 2;   // groupID
    int t4   = lane & 3;    // threadID_in_group
    int row0 = blockIdx.x * 128;

    float acc1[12][4];
    float acc2[12][4];
#pragma unroll
    for (int nt = 0; nt < 12; nt++)
#pragma unroll
        for (int j = 0; j < 4; j++) { acc1[nt][j] = 0.f; acc2[nt][j] = 0.f; }

    for (int kc = 0; kc < D; kc += 32) {
        // stage A chunk 128x32 (coalesced gmem reads)
#pragma unroll
        for (int i = 0; i < 16; i++) {
            int lin = t + i * 256;
            int r = lin >> 5;
            int k = lin & 31;
            int grow = row0 + r;
            float v = (grow < NN) ? h[grow * D + kc + k] : 0.f;
            sA[r * 36 + k] = f2tf32(v);
        }
        // stage W chunks 96x32 each, n-major in smem
#pragma unroll
        for (int i = 0; i < 12; i++) {
            int lin = t + i * 256;
            int k = lin / 96;            // 0..31
            int n = lin - k * 96;        // 0..95
            sW1[n * 36 + k] = f2tf32(W1[(kc + k) * D + n]);
            sW2[n * 36 + k] = f2tf32(W2[(kc + k) * D + n]);
        }
        __syncthreads();

#pragma unroll
        for (int ks = 0; ks < 4; ks++) {
            int k0 = ks * 8;
            int ra = (warp * 16 + gq) * 36 + k0 + t4;
            uint32_t a0 = sA[ra];
            uint32_t a1 = sA[ra + 8 * 36];
            uint32_t a2 = sA[ra + 4];
            uint32_t a3 = sA[ra + 8 * 36 + 4];
#pragma unroll
            for (int nt = 0; nt < 12; nt++) {
                int bi = (nt * 8 + gq) * 36 + k0 + t4;
                uint32_t b0 = sW1[bi], b1 = sW1[bi + 4];
                mma_tf32(acc1[nt], a0, a1, a2, a3, b0, b1);
                uint32_t c0 = sW2[bi], c1 = sW2[bi + 4];
                mma_tf32(acc2[nt], a0, a1, a2, a3, c0, c1);
            }
        }
        __syncthreads();
    }

    // epilogue: D-frag layout (row gq / gq+8, col 2*t4, 2*t4+1)
    int row = row0 + warp * 16 + gq;
#pragma unroll
    for (int nt = 0; nt < 12; nt++) {
        int col = nt * 8 + 2 * t4;
        if (row < NN) {
            *(float2*)&g_self[row * D + col] = make_float2(acc1[nt][0], acc1[nt][1]);
            *(float2*)&g_msg [row * D + col] = make_float2(acc2[nt][0], acc2[nt][1]);
        }
        if (row + 8 < NN) {
            *(float2*)&g_self[(row + 8) * D + col] = make_float2(acc1[nt][2], acc1[nt][3]);
            *(float2*)&g_msg [(row + 8) * D + col] = make_float2(acc2[nt][2], acc2[nt][3]);
        }
    }
}

// ---------------- aggregation: h_out = relu(self + sum_{in-edges} msg[src]) ----------------
// one warp per node; lanes 0..23 each own 4 contiguous dims (float4 = 1 LDG.128/edge/lane)
__global__ void k_aggregate(int houtcode) {
    int gt   = blockIdx.x * blockDim.x + threadIdx.x;
    int w    = gt >> 5;
    int lane = gt & 31;
    if (w >= NN || lane >= 24) return;
    float4* __restrict__ hout = (float4*)((houtcode == 1) ? g_h0 : g_h1);

    const float4* __restrict__ M = (const float4*)g_msg;
    float4 a = make_float4(0.f, 0.f, 0.f, 0.f);
    int s = g_ptr[w];
    int e = g_ptr[w + 1];
    for (int i = s; i < e; i++) {
        float4 m = M[(size_t)g_srcs[i] * 24 + lane];
        a.x += m.x; a.y += m.y; a.z += m.z; a.w += m.w;
    }
    const float4* __restrict__ S = (const float4*)g_self;
    float4 sp = S[(size_t)w * 24 + lane];
    float4 r;
    r.x = fmaxf(sp.x + a.x, 0.f);
    r.y = fmaxf(sp.y + a.y, 0.f);
    r.z = fmaxf(sp.z + a.z, 0.f);
    r.w = fmaxf(sp.w + a.w, 0.f);
    hout[(size_t)w * 24 + lane] = r;
}

// ---------------- graph pooling ----------------
__device__ __forceinline__ int lowerb(const int* __restrict__ a, int n, int v) {
    int lo = 0, hi = n;
    while (lo < hi) {
        int mid = (lo + hi) >> 1;
        if (a[mid] < v) lo = mid + 1; else hi = mid;
    }
    return lo;
}

__global__ void k_pool(const int* __restrict__ batch) {
    __shared__ int   se[2];
    __shared__ float red[4][96];
    int g = blockIdx.x;
    int t = threadIdx.x;
    if (t == 0) se[0] = lowerb(batch, NN, g);
    if (t == 1) se[1] = lowerb(batch, NN, g + 1);
    __syncthreads();
    int d = t % 96;
    int q = t / 96;
    int s0 = se[0], s1 = se[1];
    float s = 0.f;
    for (int n = s0 + q; n < s1; n += 4) s += g_h0[(size_t)n * D + d];
    red[q][d] = s;
    __syncthreads();
    if (q == 0) g_emb[g * D + d] = red[0][d] + red[1][d] + red[2][d] + red[3][d];
}

// ---------------- MLP head ----------------
__global__ void k_mlp(const float* __restrict__ cw1, const float* __restrict__ cb1,
                      const float* __restrict__ cw2, const float* __restrict__ cb2,
                      float* __restrict__ out) {
    __shared__ float emb[96];
    __shared__ float hid[96];
    int g = blockIdx.x;
    int d = threadIdx.x;  // 96 threads
    emb[d] = g_emb[g * D + d];
    __syncthreads();
    float s = cb1[d];
#pragma unroll 8
    for (int k = 0; k < 96; k++) s += emb[k] * cw1[k * D + d];
    hid[d] = fmaxf(s, 0.f);
    __syncthreads();
    if (d < OD) {
        float o = cb2[d];
#pragma unroll 8
        for (int k = 0; k < 96; k++) o += hid[k] * cw2[k * OD + d];
        out[g * OD + d] = o;
    }
}

// ---------------- launch ----------------
extern "C" void kernel_launch(void* const* d_in, const int* in_sizes, int n_in,
                              void* d_out, int out_size) {
    const float* x     = (const float*)d_in[0];
    const int*   ei    = (const int*)  d_in[1];
    const int*   batch = (const int*)  d_in[2];
    const float* W1    = (const float*)d_in[3];
    const float* W2    = (const float*)d_in[4];
    const float* cw1   = (const float*)d_in[5];
    const float* cb1   = (const float*)d_in[6];
    const float* cw2   = (const float*)d_in[7];
    const float* cb2   = (const float*)d_in[8];
    float* out = (float*)d_out;

    const int* src = ei;        // edge_index[0]
    const int* dst = ei + NE;   // edge_index[1]

    // CSR build (edge structure is layer-invariant: build once per launch)
    k_zero<<<(NN + 255) / 256, 256>>>();
    k_hist<<<(NE + 255) / 256, 256>>>(dst);
    k_scan<<<1, 1024>>>();
    k_fill<<<(NE + 255) / 256, 256>>>(src, dst);

    const int gemm_grid = (NN + 127) / 128;
    const int agg_grid  = (NN * 32 + 255) / 256;

    // layer 0: x -> g_h0
    k_gemm_dual_tc<<<gemm_grid, 256>>>(x, 0, W1 + 0 * D * D, W2 + 0 * D * D);
    k_aggregate<<<agg_grid, 256>>>(1);
    // layer 1: g_h0 -> g_h1
    k_gemm_dual_tc<<<gemm_grid, 256>>>(x, 1, W1 + 1 * D * D, W2 + 1 * D * D);
    k_aggregate<<<agg_grid, 256>>>(2);
    // layer 2: g_h1 -> g_h0
    k_gemm_dual_tc<<<gemm_grid, 256>>>(x, 2, W1 + 2 * D * D, W2 + 2 * D * D);
    k_aggregate<<<agg_grid, 256>>>(1);

    k_pool<<<NG, 384>>>(batch);
    k_mlp<<<NG, 96>>>(cw1, cb1, cw2, cb2, out);
}

// round 3
// speedup vs baseline: 1.6501x; 1.1947x over previous
#include <cuda_runtime.h>
#include <cstdint>

#define NN 50000
#define NE 800000
#define D  96
#define NG 128
#define OD 10

// ---------------- scratch (static device globals; no allocation) ----------------
__device__ __align__(16) float g_self[NN * D];
__device__ __align__(16) float g_msg [NN * D];
__device__ __align__(16) float g_h0  [NN * D];
__device__ __align__(16) float g_h1  [NN * D];
__device__ int   g_deg [NN];
__device__ int   g_cnt [NN];
__device__ int   g_ptr [NN + 1];
__device__ int   g_srcs[NE];
__device__ float g_emb [NG * D];

// ---------------- CSR build ----------------
__global__ void k_hist(const int* __restrict__ dst) {
    int e = blockIdx.x * blockDim.x + threadIdx.x;
    if (e < NE) atomicAdd(&g_deg[dst[e]], 1);
}

// single-block exclusive scan over g_deg -> g_ptr
__global__ void k_scan() {
    __shared__ int part[1024];
    const int T = 1024;
    const int C = (NN + T - 1) / T;  // 49
    int t = threadIdx.x;
    int base = t * C;
    int s = 0;
    for (int i = 0; i < C; i++) {
        int idx = base + i;
        if (idx < NN) s += g_deg[idx];
    }
    part[t] = s;
    __syncthreads();
    for (int off = 1; off < T; off <<= 1) {
        int v = 0;
        if (t >= off) v = part[t - off];
        __syncthreads();
        if (t >= off) part[t] += v;
        __syncthreads();
    }
    int run = (t == 0) ? 0 : part[t - 1];
    for (int i = 0; i < C; i++) {
        int idx = base + i;
        if (idx < NN) { g_ptr[idx] = run; run += g_deg[idx]; }
    }
    if (t == T - 1) g_ptr[NN] = NE;
}

__global__ void k_fill(const int* __restrict__ src, const int* __restrict__ dst) {
    int e = blockIdx.x * blockDim.x + threadIdx.x;
    if (e < NE) {
        int d = dst[e];
        int pos = g_ptr[d] + atomicAdd(&g_cnt[d], 1);
        g_srcs[pos] = src[e];
    }
}

// ---------------- tf32 helpers ----------------
__device__ __forceinline__ uint32_t f2tf32(float x) {
    uint32_t r;
    asm("cvt.rna.tf32.f32 %0, %1;" : "=r"(r) : "f"(x));
    return r;
}

__device__ __forceinline__ void mma_tf32(float* c,
                                         uint32_t a0, uint32_t a1, uint32_t a2, uint32_t a3,
                                         uint32_t b0, uint32_t b1) {
    asm volatile(
        "mma.sync.aligned.m16n8k8.row.col.f32.tf32.tf32.f32 "
        "{%0,%1,%2,%3}, {%4,%5,%6,%7}, {%8,%9}, {%0,%1,%2,%3};\n"
        : "+f"(c[0]), "+f"(c[1]), "+f"(c[2]), "+f"(c[3])
        : "r"(a0), "r"(a1), "r"(a2), "r"(a3), "r"(b0), "r"(b1));
}

// ---------------- fused dual GEMM on tensor cores (tf32), full-K staging ----------------
// block = 256 threads (8 warps as 4M x 2N), tile M=128, N=96, K=96 fully staged.
// Per warp: M=32 (2 m16 frags) x N=48 (6 n8 tiles) -> only 32 scalar LDS per k-step.
// A in smem: per-32k chunk, [r*36 + k] (banks gq*4+t4 : conflict-free).
// W in smem: k-major [k*104 + n]   (banks t4*8+gq : conflict-free).
#define SA_WORDS (3 * 128 * 36)
#define SW_WORDS (96 * 104)
#define GEMM_DSMEM ((SA_WORDS + 2 * SW_WORDS) * 4)

__global__ void k_gemm_dual_tc(const float* __restrict__ xin, int hcode,
                               const float* __restrict__ W1,
                               const float* __restrict__ W2) {
    const float* __restrict__ h = (hcode == 0) ? xin : ((hcode == 1) ? g_h0 : g_h1);

    extern __shared__ uint32_t smem[];
    uint32_t* sA  = smem;                  // 3 chunks x 128 x 36
    uint32_t* sW1 = smem + SA_WORDS;       // 96 x 104 (k-major)
    uint32_t* sW2 = sW1 + SW_WORDS;

    int t     = threadIdx.x;
    int warp  = t >> 5;
    int lane  = t & 31;
    int gq    = lane >> 2;     // 0..7
    int t4    = lane & 3;      // 0..3
    int warpM = warp >> 1;     // 0..3
    int warpN = warp & 1;      // 0..1
    int row0  = blockIdx.x * 128;

    // ---- stage A: 128 x 96, coalesced scalar ----
#pragma unroll
    for (int i = 0; i < 48; i++) {
        int lin = t + i * 256;
        int r = lin / 96;
        int k = lin - r * 96;
        int c = k >> 5;
        int kw = k & 31;
        int grow = row0 + r;
        float v = (grow < NN) ? h[grow * D + k] : 0.f;
        sA[c * (128 * 36) + r * 36 + kw] = f2tf32(v);
    }
    // ---- stage W1/W2: 96 x 96 each, k-major ----
#pragma unroll
    for (int i = 0; i < 36; i++) {
        int lin = t + i * 256;
        int k = lin / 96;
        int n = lin - k * 96;
        sW1[k * 104 + n] = f2tf32(W1[k * D + n]);
        sW2[k * 104 + n] = f2tf32(W2[k * D + n]);
    }
    __syncthreads();

    float acc1[2][6][4];
    float acc2[2][6][4];
#pragma unroll
    for (int mt = 0; mt < 2; mt++)
#pragma unroll
        for (int nt = 0; nt < 6; nt++)
#pragma unroll
            for (int j = 0; j < 4; j++) { acc1[mt][nt][j] = 0.f; acc2[mt][nt][j] = 0.f; }

#pragma unroll
    for (int c = 0; c < 3; c++) {
#pragma unroll
        for (int ks = 0; ks < 4; ks++) {
            int k0 = ks * 8;
            // A fragments for 2 m16 tiles
            uint32_t a0[2], a1[2], a2[2], a3[2];
#pragma unroll
            for (int mt = 0; mt < 2; mt++) {
                int r = warpM * 32 + mt * 16 + gq;
                int idx = c * (128 * 36) + r * 36 + k0 + t4;
                a0[mt] = sA[idx];
                a1[mt] = sA[idx + 8 * 36];
                a2[mt] = sA[idx + 4];
                a3[mt] = sA[idx + 8 * 36 + 4];
            }
            int kg = c * 32 + k0;
#pragma unroll
            for (int nt = 0; nt < 6; nt++) {
                int n = warpN * 48 + nt * 8 + gq;
                int bi = (kg + t4) * 104 + n;
                uint32_t b0 = sW1[bi];
                uint32_t b1 = sW1[bi + 4 * 104];
                uint32_t c0 = sW2[bi];
                uint32_t c1 = sW2[bi + 4 * 104];
#pragma unroll
                for (int mt = 0; mt < 2; mt++) {
                    mma_tf32(acc1[mt][nt], a0[mt], a1[mt], a2[mt], a3[mt], b0, b1);
                    mma_tf32(acc2[mt][nt], a0[mt], a1[mt], a2[mt], a3[mt], c0, c1);
                }
            }
        }
    }

    // ---- epilogue ----
#pragma unroll
    for (int mt = 0; mt < 2; mt++) {
        int row = row0 + warpM * 32 + mt * 16 + gq;
#pragma unroll
        for (int nt = 0; nt < 6; nt++) {
            int col = warpN * 48 + nt * 8 + 2 * t4;
            if (row < NN) {
                *(float2*)&g_self[row * D + col] = make_float2(acc1[mt][nt][0], acc1[mt][nt][1]);
                *(float2*)&g_msg [row * D + col] = make_float2(acc2[mt][nt][0], acc2[mt][nt][1]);
            }
            if (row + 8 < NN) {
                *(float2*)&g_self[(row + 8) * D + col] = make_float2(acc1[mt][nt][2], acc1[mt][nt][3]);
                *(float2*)&g_msg [(row + 8) * D + col] = make_float2(acc2[mt][nt][2], acc2[mt][nt][3]);
            }
        }
    }
}

// ---------------- aggregation: h_out = relu(self + sum_{in-edges} msg[src]) ----------------
// one warp per node; lanes 0..23 each own 4 contiguous dims (1 LDG.128/edge/lane)
__global__ void k_aggregate(int houtcode) {
    int gt   = blockIdx.x * blockDim.x + threadIdx.x;
    int w    = gt >> 5;
    int lane = gt & 31;
    if (w >= NN || lane >= 24) return;
    float4* __restrict__ hout = (float4*)((houtcode == 1) ? g_h0 : g_h1);

    const float4* __restrict__ M = (const float4*)g_msg;
    float4 a = make_float4(0.f, 0.f, 0.f, 0.f);
    int s = g_ptr[w];
    int e = g_ptr[w + 1];
    for (int i = s; i < e; i++) {
        float4 m = M[(size_t)g_srcs[i] * 24 + lane];
        a.x += m.x; a.y += m.y; a.z += m.z; a.w += m.w;
    }
    const float4* __restrict__ S = (const float4*)g_self;
    float4 sp = S[(size_t)w * 24 + lane];
    float4 r;
    r.x = fmaxf(sp.x + a.x, 0.f);
    r.y = fmaxf(sp.y + a.y, 0.f);
    r.z = fmaxf(sp.z + a.z, 0.f);
    r.w = fmaxf(sp.w + a.w, 0.f);
    hout[(size_t)w * 24 + lane] = r;
}

// ---------------- graph pooling ----------------
__device__ __forceinline__ int lowerb(const int* __restrict__ a, int n, int v) {
    int lo = 0, hi = n;
    while (lo < hi) {
        int mid = (lo + hi) >> 1;
        if (a[mid] < v) lo = mid + 1; else hi = mid;
    }
    return lo;
}

__global__ void k_pool(const int* __restrict__ batch) {
    __shared__ int   se[2];
    __shared__ float red[4][96];
    int g = blockIdx.x;
    int t = threadIdx.x;
    if (t == 0) se[0] = lowerb(batch, NN, g);
    if (t == 1) se[1] = lowerb(batch, NN, g + 1);
    __syncthreads();
    int d = t % 96;
    int q = t / 96;
    int s0 = se[0], s1 = se[1];
    float s = 0.f;
    for (int n = s0 + q; n < s1; n += 4) s += g_h0[(size_t)n * D + d];
    red[q][d] = s;
    __syncthreads();
    if (q == 0) g_emb[g * D + d] = red[0][d] + red[1][d] + red[2][d] + red[3][d];
}

// ---------------- MLP head ----------------
__global__ void k_mlp(const float* __restrict__ cw1, const float* __restrict__ cb1,
                      const float* __restrict__ cw2, const float* __restrict__ cb2,
                      float* __restrict__ out) {
    __shared__ float emb[96];
    __shared__ float hid[96];
    int g = blockIdx.x;
    int d = threadIdx.x;  // 96 threads
    emb[d] = g_emb[g * D + d];
    __syncthreads();
    float s = cb1[d];
#pragma unroll 8
    for (int k = 0; k < 96; k++) s += emb[k] * cw1[k * D + d];
    hid[d] = fmaxf(s, 0.f);
    __syncthreads();
    if (d < OD) {
        float o = cb2[d];
#pragma unroll 8
        for (int k = 0; k < 96; k++) o += hid[k] * cw2[k * OD + d];
        out[g * OD + d] = o;
    }
}

// ---------------- launch ----------------
extern "C" void kernel_launch(void* const* d_in, const int* in_sizes, int n_in,
                              void* d_out, int out_size) {
    const float* x     = (const float*)d_in[0];
    const int*   ei    = (const int*)  d_in[1];
    const int*   batch = (const int*)  d_in[2];
    const float* W1    = (const float*)d_in[3];
    const float* W2    = (const float*)d_in[4];
    const float* cw1   = (const float*)d_in[5];
    const float* cb1   = (const float*)d_in[6];
    const float* cw2   = (const float*)d_in[7];
    const float* cb2   = (const float*)d_in[8];
    float* out = (float*)d_out;

    const int* src = ei;        // edge_index[0]
    const int* dst = ei + NE;   // edge_index[1]

    cudaFuncSetAttribute(k_gemm_dual_tc,
                         cudaFuncAttributeMaxDynamicSharedMemorySize, GEMM_DSMEM);

    // CSR build (layer-invariant: built once per launch)
    void *p_deg = nullptr, *p_cnt = nullptr;
    cudaGetSymbolAddress(&p_deg, g_deg);
    cudaGetSymbolAddress(&p_cnt, g_cnt);
    cudaMemsetAsync(p_deg, 0, NN * sizeof(int));
    cudaMemsetAsync(p_cnt, 0, NN * sizeof(int));
    k_hist<<<(NE + 255) / 256, 256>>>(dst);
    k_scan<<<1, 1024>>>();
    k_fill<<<(NE + 255) / 256, 256>>>(src, dst);

    const int gemm_grid = (NN + 127) / 128;
    const int agg_grid  = (NN * 32 + 255) / 256;

    // layer 0: x -> g_h0
    k_gemm_dual_tc<<<gemm_grid, 256, GEMM_DSMEM>>>(x, 0, W1 + 0 * D * D, W2 + 0 * D * D);
    k_aggregate<<<agg_grid, 256>>>(1);
    // layer 1: g_h0 -> g_h1
    k_gemm_dual_tc<<<gemm_grid, 256, GEMM_DSMEM>>>(x, 1, W1 + 1 * D * D, W2 + 1 * D * D);
    k_aggregate<<<agg_grid, 256>>>(2);
    // layer 2: g_h1 -> g_h0
    k_gemm_dual_tc<<<gemm_grid, 256, GEMM_DSMEM>>>(x, 2, W1 + 2 * D * D, W2 + 2 * D * D);
    k_aggregate<<<agg_grid, 256>>>(1);

    k_pool<<<NG, 384>>>(batch);
    k_mlp<<<NG, 96>>>(cw1, cb1, cw2, cb2, out);
}